// round 9
// baseline (speedup 1.0000x reference)
#include <cuda_runtime.h>
#include <cuda_bf16.h>
#include <math.h>
#include <float.h>
#include <stdint.h>

#define N_NODES 50000
#define N_EDGES 800000
#define DIM 128
#define EDIM 32
#define NB_SCAN ((N_NODES + 1023) / 1024)   // 49 scan blocks

// ---------------- scratch (static device allocations) ----------------
__device__ float g_z[N_NODES * DIM];      // projected features
__device__ float g_ssrc[N_NODES];
__device__ float g_sdst[N_NODES];
__device__ float g_t[N_EDGES];            // efeats @ a_e  (edge-local score part)
__device__ int   g_cnt[N_NODES];
__device__ int   g_lex[N_NODES];          // block-local exclusive scan
__device__ int   g_bsum[64];
__device__ int   g_off[N_NODES + 1];
__device__ int   g_cur[N_NODES];
__device__ uint2 g_pair[N_EDGES];         // (src, bits(t)) permuted into CSR-by-dst order

// init: zero counters only (W split now inline in the GEMM)
__global__ __launch_bounds__(256) void init_kernel() {
    int i = blockIdx.x * blockDim.x + threadIdx.x;
    if (i < N_NODES) g_cnt[i] = 0;
    if (i == 0) g_off[N_NODES] = N_EDGES;
}

// ============ manual mma.sync bf16 GEMM: z = nfeats @ W_fc^T ==================
// 2-split, 3 passes (AhWh + AhWl + AlWh), fp32 accum. rel err ~1e-5.
// Block: 256 threads (8 warps) = 64 rows x 128 cols. Warp w: n0 = w*16.
#define APAD 136           // bf16 row pad (272B rows: conflict-free ldmatrix)
#define WPAD 136
#define ZPAD 132           // f32 row pad for epilogue tile
// dynamic smem layout (bytes):
#define SMG_AH   0
#define SMG_AL   17408                          // 64*136*2
#define SMG_WH   34816
#define SMG_WL   (34816 + 34816)                // 69632  (128*136*2 each)
#define SMG_ATTN 104448
#define SMG_TOTAL (SMG_ATTN + 256 * 4)          // 105472
#define SMG_ZT   0                              // f32 z tile overlays A after MMA

#define LDSM4(R, addr) \
    asm volatile("ldmatrix.sync.aligned.m8n8.x4.shared.b16 {%0,%1,%2,%3}, [%4];" \
        : "=r"((R)[0]), "=r"((R)[1]), "=r"((R)[2]), "=r"((R)[3]) : "r"(addr))

#define MMA_BF16(C, AR, B0, B1) \
    asm volatile("mma.sync.aligned.m16n8k16.row.col.f32.bf16.bf16.f32 " \
        "{%0,%1,%2,%3}, {%4,%5,%6,%7}, {%8,%9}, {%0,%1,%2,%3};" \
        : "+f"((C)[0]), "+f"((C)[1]), "+f"((C)[2]), "+f"((C)[3]) \
        : "r"((AR)[0]), "r"((AR)[1]), "r"((AR)[2]), "r"((AR)[3]), "r"(B0), "r"(B1))

__device__ __forceinline__ void split_store(__nv_bfloat16* sh, __nv_bfloat16* sl,
                                            int off, float4 v) {
    float f[4] = {v.x, v.y, v.z, v.w};
    uint16_t hh[4], ll[4];
#pragma unroll
    for (int q = 0; q < 4; q++) {
        __nv_bfloat16 h = __float2bfloat16(f[q]);
        hh[q] = __bfloat16_as_ushort(h);
        ll[q] = __bfloat16_as_ushort(__float2bfloat16(f[q] - __bfloat162float(h)));
    }
    *(uint2*)&sh[off] = make_uint2((uint32_t)hh[0] | ((uint32_t)hh[1] << 16),
                                   (uint32_t)hh[2] | ((uint32_t)hh[3] << 16));
    *(uint2*)&sl[off] = make_uint2((uint32_t)ll[0] | ((uint32_t)ll[1] << 16),
                                   (uint32_t)ll[2] | ((uint32_t)ll[3] << 16));
}

__global__ void __launch_bounds__(256) gemm_mma_kernel(const float* __restrict__ A,
                                                       const float* __restrict__ W,
                                                       const float* __restrict__ Wattn) {
    extern __shared__ char smem[];
    __nv_bfloat16* sAh = (__nv_bfloat16*)(smem + SMG_AH);
    __nv_bfloat16* sAl = (__nv_bfloat16*)(smem + SMG_AL);
    __nv_bfloat16* sWh = (__nv_bfloat16*)(smem + SMG_WH);
    __nv_bfloat16* sWl = (__nv_bfloat16*)(smem + SMG_WL);
    float* szt  = (float*)(smem + SMG_ZT);
    float* asrc = (float*)(smem + SMG_ATTN);
    float* adst = asrc + 128;

    int tid = threadIdx.x;
    int wid = tid >> 5, lane = tid & 31;
    int i0 = blockIdx.x * 64;
    int n0 = wid * 16;

    if (tid < 128) {
        asrc[tid] = Wattn[tid];
        adst[tid] = Wattn[DIM + EDIM + tid];
    }

    // stage W fp32 -> split bf16 hi/lo into smem (W is L2-hot, 64 KB)
#pragma unroll
    for (int t = 0; t < 16; t++) {
        int idx = tid + t * 256;            // 4096 float4
        int row = idx >> 5, col = (idx & 31) * 4;
        float4 wv = *(const float4*)&W[row * 128 + col];
        split_store(sWh, sWl, row * WPAD + col, wv);
    }

    // load A 64x128 fp32, split to bf16 hi/lo in smem
#pragma unroll
    for (int t = 0; t < 8; t++) {
        int idx = tid + t * 256;            // 2048 float4
        int row = idx >> 5, col = (idx & 31) * 4;
        int gr = i0 + row;
        float4 av = make_float4(0.f, 0.f, 0.f, 0.f);
        if (gr < N_NODES) av = *(const float4*)&A[gr * 128 + col];
        split_store(sAh, sAl, row * APAD + col, av);
    }
    __syncthreads();

    // ldmatrix lane addresses (byte offsets in shared space)
    uint32_t sb = (uint32_t)__cvta_generic_to_shared(smem);
    uint32_t aoff = (uint32_t)(((lane & 15) * APAD + (lane >> 4) * 8) * 2);
    uint32_t aH = sb + SMG_AH + aoff;
    uint32_t aL = sb + SMG_AL + aoff;
    uint32_t boff = (uint32_t)(((n0 + ((lane >> 4) << 3) + (lane & 7)) * WPAD
                                + (((lane >> 3) & 1) << 3)) * 2);
    uint32_t bH = sb + SMG_WH + boff;
    uint32_t bL = sb + SMG_WL + boff;

    float c[4][2][4];
#pragma unroll
    for (int m = 0; m < 4; m++)
#pragma unroll
        for (int g = 0; g < 2; g++)
#pragma unroll
            for (int q = 0; q < 4; q++) c[m][g][q] = 0.f;

#pragma unroll
    for (int pass = 0; pass < 3; pass++) {
        uint32_t ab = (pass == 2) ? aL : aH;
        uint32_t bb = (pass == 1) ? bL : bH;
#pragma unroll
        for (int k = 0; k < 8; k++) {
            uint32_t br[4];
            LDSM4(br, bb + k * 32);             // 16 bf16 cols = 32B
#pragma unroll
            for (int m = 0; m < 4; m++) {
                uint32_t ar[4];
                LDSM4(ar, ab + (uint32_t)((m * 16 * APAD + k * 16) * 2));
                MMA_BF16(c[m][0], ar, br[0], br[1]);
                MMA_BF16(c[m][1], ar, br[2], br[3]);
            }
        }
    }

    __syncthreads();   // all warps done reading sA before z-tile overlay

    // accumulators -> smem z tile (m16n8 f32 frag layout)
#pragma unroll
    for (int m = 0; m < 4; m++)
#pragma unroll
        for (int g = 0; g < 2; g++) {
            int row = m * 16 + (lane >> 2);
            int col = n0 + g * 8 + (lane & 3) * 2;
            *(float2*)&szt[row * ZPAD + col] = make_float2(c[m][g][0], c[m][g][1]);
            *(float2*)&szt[(row + 8) * ZPAD + col] = make_float2(c[m][g][2], c[m][g][3]);
        }
    __syncthreads();

    // s_src / s_dst: thread t -> row t>>2, quarter t&3 (32 cols), 4-lane reduce
    {
        int r = tid >> 2, q = tid & 3;
        const float* zr = szt + r * ZPAD + q * 32;
        float ps = 0.f, pd = 0.f;
#pragma unroll
        for (int cc = 0; cc < 32; cc++) {
            float v = zr[cc];
            ps += v * asrc[q * 32 + cc];
            pd += v * adst[q * 32 + cc];
        }
        ps += __shfl_xor_sync(0xffffffffu, ps, 1);
        pd += __shfl_xor_sync(0xffffffffu, pd, 1);
        ps += __shfl_xor_sync(0xffffffffu, ps, 2);
        pd += __shfl_xor_sync(0xffffffffu, pd, 2);
        int gr = i0 + r;
        if (q == 0 && gr < N_NODES) { g_ssrc[gr] = ps; g_sdst[gr] = pd; }
    }

    // coalesced z store
#pragma unroll
    for (int t = 0; t < 8; t++) {
        int idx = tid + t * 256;
        int row = idx >> 5, col = (idx & 31) * 4;
        int gr = i0 + row;
        if (gr < N_NODES) {
            float4 v = *(const float4*)&szt[row * ZPAD + col];
            *(float4*)&g_z[gr * 128 + col] = v;
        }
    }
}

// ---------------- edge score (efeats stream only; independent branch) ---------
#define DOT4(A, B) ((A).x*(B).x + (A).y*(B).y + (A).z*(B).z + (A).w*(B).w)

__global__ __launch_bounds__(256) void edge_score_kernel(const float* __restrict__ efeats,
                                                         const float* __restrict__ Wattn) {
    int gid = blockIdx.x * blockDim.x + threadIdx.x;
    int e = gid >> 2;
    int l = gid & 3;
    if (e >= N_EDGES) return;
    const float* erow = &efeats[e * EDIM + l * 8];
    float4 ev0 = *(const float4*)&erow[0];
    float4 ev1 = *(const float4*)&erow[4];
    float4 av0 = *(const float4*)&Wattn[DIM + l * 8];
    float4 av1 = *(const float4*)&Wattn[DIM + l * 8 + 4];
    float p = DOT4(ev0, av0) + DOT4(ev1, av1);
    p += __shfl_xor_sync(0xffffffffu, p, 2);
    p += __shfl_xor_sync(0xffffffffu, p, 1);
    if (l == 0) g_t[e] = p;
}

// ---------------- histogram of dst (int4, 4 atomics per thread) ----------------
__global__ __launch_bounds__(256) void hist_kernel(const int* __restrict__ dst) {
    int i = blockIdx.x * blockDim.x + threadIdx.x;   // int4 index
    if (i * 4 < N_EDGES) {
        int4 d = *(const int4*)&dst[i * 4];
        atomicAdd(&g_cnt[d.x], 1);
        atomicAdd(&g_cnt[d.y], 1);
        atomicAdd(&g_cnt[d.z], 1);
        atomicAdd(&g_cnt[d.w], 1);
    }
}

// ---------------- parallel scan, phase 1 ----------------
__global__ __launch_bounds__(1024) void scan1_kernel() {
    __shared__ int ws[32];
    int t = threadIdx.x, b = blockIdx.x;
    int i = b * 1024 + t;
    int lane = t & 31, w = t >> 5;
    int c = (i < N_NODES) ? g_cnt[i] : 0;
    int v = c;
#pragma unroll
    for (int o = 1; o < 32; o <<= 1) {
        int n = __shfl_up_sync(0xffffffffu, v, o);
        if (lane >= o) v += n;
    }
    if (lane == 31) ws[w] = v;
    __syncthreads();
    if (w == 0) {
        int s = ws[lane];
#pragma unroll
        for (int o = 1; o < 32; o <<= 1) {
            int n = __shfl_up_sync(0xffffffffu, s, o);
            if (lane >= o) s += n;
        }
        ws[lane] = s;
    }
    __syncthreads();
    int pre = (w > 0) ? ws[w - 1] : 0;
    if (i < N_NODES) g_lex[i] = pre + v - c;
    if (t == 0) g_bsum[b] = ws[31];
}

// ---------------- phase 2+3 merged: every block scans the 49 block sums -------
__global__ __launch_bounds__(256) void scan23_kernel() {
    __shared__ int sb[64];
    int t = threadIdx.x;
    if (t < 64) {
        int v = (t < NB_SCAN) ? g_bsum[t] : 0;
        sb[t] = v;
    }
    __syncthreads();
    if (t < 64) {
        int v = sb[t];
        int incl = v;
#pragma unroll
        for (int o = 1; o < 64; o <<= 1) {
            int n = (t >= o) ? sb[t - o] : 0;
            __syncthreads();
            incl += n;
            sb[t] = incl;
            __syncthreads();
        }
        sb[t] = incl - v;   // exclusive prefix
    } else {
#pragma unroll
        for (int o = 1; o < 64; o <<= 1) { __syncthreads(); __syncthreads(); }
    }
    __syncthreads();
    int i = blockIdx.x * blockDim.x + t;
    if (i < N_NODES) {
        int off = g_lex[i] + sb[i >> 10];
        g_off[i] = off;
        g_cur[i] = off;
    }
}

// ---------------- scatter: join branch, build CSR pairs ----------------
__global__ __launch_bounds__(256) void scatter_kernel(const int* __restrict__ src,
                                                      const int* __restrict__ dst) {
    int e = blockIdx.x * blockDim.x + threadIdx.x;
    if (e >= N_EDGES) return;
    int s = src[e];
    int d = dst[e];
    float t = g_t[e] + g_ssrc[s];
    int pos = atomicAdd(&g_cur[d], 1);
    g_pair[pos] = make_uint2((unsigned)s, __float_as_uint(t));
}

// ---------------- warp-per-node single-pass softmax + aggregation -------------
__global__ __launch_bounds__(256) void aggregate_kernel(float* __restrict__ h) {
    int gid = blockIdx.x * blockDim.x + threadIdx.x;
    int node = gid >> 5;
    int lane = gid & 31;
    if (node >= N_NODES) return;

    int beg = g_off[node];
    int end = g_off[node + 1];

    float acc0 = 0.f, acc1 = 0.f, acc2 = 0.f, acc3 = 0.f;

    if (beg < end) {
        float sd = g_sdst[node];
        float lsum = 0.f;

        for (int j0 = beg; j0 < end; j0 += 32) {
            int j = j0 + lane;
            float wgt = 0.f;
            int sidx = 0;
            if (j < end) {
                uint2 pr = g_pair[j];
                float x = __uint_as_float(pr.y) + sd;
                x = x > 0.f ? x : 0.01f * x;
                wgt = __expf(x);
                sidx = (int)pr.x;
            }
            lsum += wgt;
            int cnt = end - j0;
            if (cnt > 32) cnt = 32;
            int q = 0;
            for (; q + 4 <= cnt; q += 4) {
                float a0 = __shfl_sync(0xffffffffu, wgt, q + 0);
                float a1 = __shfl_sync(0xffffffffu, wgt, q + 1);
                float a2 = __shfl_sync(0xffffffffu, wgt, q + 2);
                float a3 = __shfl_sync(0xffffffffu, wgt, q + 3);
                int s0 = __shfl_sync(0xffffffffu, sidx, q + 0);
                int s1 = __shfl_sync(0xffffffffu, sidx, q + 1);
                int s2 = __shfl_sync(0xffffffffu, sidx, q + 2);
                int s3 = __shfl_sync(0xffffffffu, sidx, q + 3);
                float4 z0 = *(const float4*)&g_z[s0 * 128 + lane * 4];
                float4 z1 = *(const float4*)&g_z[s1 * 128 + lane * 4];
                float4 z2 = *(const float4*)&g_z[s2 * 128 + lane * 4];
                float4 z3 = *(const float4*)&g_z[s3 * 128 + lane * 4];
                acc0 += a0 * z0.x; acc1 += a0 * z0.y; acc2 += a0 * z0.z; acc3 += a0 * z0.w;
                acc0 += a1 * z1.x; acc1 += a1 * z1.y; acc2 += a1 * z1.z; acc3 += a1 * z1.w;
                acc0 += a2 * z2.x; acc1 += a2 * z2.y; acc2 += a2 * z2.z; acc3 += a2 * z2.w;
                acc0 += a3 * z3.x; acc1 += a3 * z3.y; acc2 += a3 * z3.z; acc3 += a3 * z3.w;
            }
            for (; q < cnt; q++) {
                float al = __shfl_sync(0xffffffffu, wgt, q);
                int sq = __shfl_sync(0xffffffffu, sidx, q);
                float4 zv = *(const float4*)&g_z[sq * 128 + lane * 4];
                acc0 += al * zv.x; acc1 += al * zv.y; acc2 += al * zv.z; acc3 += al * zv.w;
            }
        }

#pragma unroll
        for (int o = 16; o; o >>= 1) lsum += __shfl_xor_sync(0xffffffffu, lsum, o);
        float inv = 1.0f / lsum;
        acc0 *= inv; acc1 *= inv; acc2 *= inv; acc3 *= inv;
    }

    float4 o4 = make_float4(acc0, acc1, acc2, acc3);
    *(float4*)&h[node * 128 + lane * 4] = o4;
}

// ---------------- launcher (multi-branch graph via event forks) ----------------
extern "C" void kernel_launch(void* const* d_in, const int* in_sizes, int n_in,
                              void* d_out, int out_size) {
    const float* nfeats = (const float*)d_in[0];
    const float* efeats = (const float*)d_in[1];
    const float* W_fc   = (const float*)d_in[2];
    const float* W_attn = (const float*)d_in[3];
    const int*   src    = (const int*)d_in[4];
    const int*   dst    = (const int*)d_in[5];
    float* out = (float*)d_out;

    // lazy host-side resources (streams/events are not device memory)
    static cudaStream_t s1 = nullptr, s2 = nullptr;
    static cudaEvent_t evFork = nullptr, evG = nullptr, evE = nullptr;
    if (s1 == nullptr) {
        cudaStreamCreateWithFlags(&s1, cudaStreamNonBlocking);
        cudaStreamCreateWithFlags(&s2, cudaStreamNonBlocking);
        cudaEventCreateWithFlags(&evFork, cudaEventDisableTiming);
        cudaEventCreateWithFlags(&evG, cudaEventDisableTiming);
        cudaEventCreateWithFlags(&evE, cudaEventDisableTiming);
        cudaFuncSetAttribute(gemm_mma_kernel, cudaFuncAttributeMaxDynamicSharedMemorySize,
                             SMG_TOTAL);
    }

    // fork
    cudaEventRecord(evFork, 0);
    cudaStreamWaitEvent(s1, evFork, 0);
    cudaStreamWaitEvent(s2, evFork, 0);

    // branch 1: projection GEMM (+ s_src/s_dst epilogue)
    gemm_mma_kernel<<<(N_NODES + 63) / 64, 256, SMG_TOTAL, s1>>>(nfeats, W_fc, W_attn);
    cudaEventRecord(evG, s1);

    // branch 2: edge-feature score stream
    edge_score_kernel<<<(N_EDGES * 4 + 255) / 256, 256, 0, s2>>>(efeats, W_attn);
    cudaEventRecord(evE, s2);

    // main branch: CSR offsets
    init_kernel<<<(N_NODES + 255) / 256, 256>>>();
    hist_kernel<<<(N_EDGES / 4 + 255) / 256, 256>>>(dst);
    scan1_kernel<<<NB_SCAN, 1024>>>();
    scan23_kernel<<<(N_NODES + 255) / 256, 256>>>();

    // join
    cudaStreamWaitEvent(0, evG, 0);
    cudaStreamWaitEvent(0, evE, 0);

    scatter_kernel<<<(N_EDGES + 255) / 256, 256>>>(src, dst);
    aggregate_kernel<<<(N_NODES * 32 + 255) / 256, 256>>>(out);
}

// round 12
// speedup vs baseline: 1.0474x; 1.0474x over previous
#include <cuda_runtime.h>
#include <cuda_bf16.h>
#include <cuda_fp16.h>
#include <math.h>
#include <float.h>
#include <stdint.h>

#define N_NODES 50000
#define N_EDGES 800000
#define DIM 128
#define EDIM 32
#define NB_SCAN ((N_NODES + 1023) / 1024)   // 49 scan blocks

// ---------------- scratch (static device allocations) ----------------
__device__ __half g_zh[N_NODES * DIM];    // projected features (fp16 for gather BW)
__device__ float g_ssrc[N_NODES];
__device__ float g_sdst[N_NODES];
__device__ int   g_cnt[N_NODES];
__device__ int   g_lex[N_NODES];          // block-local exclusive scan
__device__ int   g_bsum[64];
__device__ int   g_off[N_NODES + 1];
__device__ int   g_cur[N_NODES];
__device__ uint2 g_pair[N_EDGES];         // (src, bits(t)) permuted into CSR-by-dst order

// init: zero counters
__global__ __launch_bounds__(256) void init_kernel() {
    int i = blockIdx.x * blockDim.x + threadIdx.x;
    if (i < N_NODES) g_cnt[i] = 0;
    if (i == 0) g_off[N_NODES] = N_EDGES;
}

// ============ manual mma.sync bf16 GEMM: z = nfeats @ W_fc^T ==================
// 2-split, 3 passes (AhWh + AhWl + AlWh), fp32 accum. rel err ~1e-5;
// z stored as fp16 (adds ~1.5e-4 RMS to downstream aggregate only).
// Block: 256 threads (8 warps) = 64 rows x 128 cols. Warp w: n0 = w*16.
#define APAD 136           // bf16 row pad (272B rows: conflict-free ldmatrix)
#define WPAD 136
#define ZPAD 132           // f32 row pad for epilogue tile
// dynamic smem layout (bytes):
#define SMG_AH   0
#define SMG_AL   17408                          // 64*136*2
#define SMG_WH   34816
#define SMG_WL   (34816 + 34816)                // 69632  (128*136*2 each)
#define SMG_ATTN 104448
#define SMG_TOTAL (SMG_ATTN + 256 * 4)          // 105472
#define SMG_ZT   0                              // f32 z tile overlays A after MMA

#define LDSM4(R, addr) \
    asm volatile("ldmatrix.sync.aligned.m8n8.x4.shared.b16 {%0,%1,%2,%3}, [%4];" \
        : "=r"((R)[0]), "=r"((R)[1]), "=r"((R)[2]), "=r"((R)[3]) : "r"(addr))

#define MMA_BF16(C, AR, B0, B1) \
    asm volatile("mma.sync.aligned.m16n8k16.row.col.f32.bf16.bf16.f32 " \
        "{%0,%1,%2,%3}, {%4,%5,%6,%7}, {%8,%9}, {%0,%1,%2,%3};" \
        : "+f"((C)[0]), "+f"((C)[1]), "+f"((C)[2]), "+f"((C)[3]) \
        : "r"((AR)[0]), "r"((AR)[1]), "r"((AR)[2]), "r"((AR)[3]), "r"(B0), "r"(B1))

__device__ __forceinline__ void split_store(__nv_bfloat16* sh, __nv_bfloat16* sl,
                                            int off, float4 v) {
    float f[4] = {v.x, v.y, v.z, v.w};
    uint16_t hh[4], ll[4];
#pragma unroll
    for (int q = 0; q < 4; q++) {
        __nv_bfloat16 h = __float2bfloat16(f[q]);
        hh[q] = __bfloat16_as_ushort(h);
        ll[q] = __bfloat16_as_ushort(__float2bfloat16(f[q] - __bfloat162float(h)));
    }
    *(uint2*)&sh[off] = make_uint2((uint32_t)hh[0] | ((uint32_t)hh[1] << 16),
                                   (uint32_t)hh[2] | ((uint32_t)hh[3] << 16));
    *(uint2*)&sl[off] = make_uint2((uint32_t)ll[0] | ((uint32_t)ll[1] << 16),
                                   (uint32_t)ll[2] | ((uint32_t)ll[3] << 16));
}

__global__ void __launch_bounds__(256) gemm_mma_kernel(const float* __restrict__ A,
                                                       const float* __restrict__ W,
                                                       const float* __restrict__ Wattn) {
    extern __shared__ char smem[];
    __nv_bfloat16* sAh = (__nv_bfloat16*)(smem + SMG_AH);
    __nv_bfloat16* sAl = (__nv_bfloat16*)(smem + SMG_AL);
    __nv_bfloat16* sWh = (__nv_bfloat16*)(smem + SMG_WH);
    __nv_bfloat16* sWl = (__nv_bfloat16*)(smem + SMG_WL);
    float* szt  = (float*)(smem + SMG_ZT);
    float* asrc = (float*)(smem + SMG_ATTN);
    float* adst = asrc + 128;

    int tid = threadIdx.x;
    int wid = tid >> 5, lane = tid & 31;
    int i0 = blockIdx.x * 64;
    int n0 = wid * 16;

    if (tid < 128) {
        asrc[tid] = Wattn[tid];
        adst[tid] = Wattn[DIM + EDIM + tid];
    }

    // stage W fp32 -> split bf16 hi/lo into smem (W is L2-hot, 64 KB)
#pragma unroll
    for (int t = 0; t < 16; t++) {
        int idx = tid + t * 256;            // 4096 float4
        int row = idx >> 5, col = (idx & 31) * 4;
        float4 wv = *(const float4*)&W[row * 128 + col];
        split_store(sWh, sWl, row * WPAD + col, wv);
    }

    // load A 64x128 fp32, split to bf16 hi/lo in smem
#pragma unroll
    for (int t = 0; t < 8; t++) {
        int idx = tid + t * 256;            // 2048 float4
        int row = idx >> 5, col = (idx & 31) * 4;
        int gr = i0 + row;
        float4 av = make_float4(0.f, 0.f, 0.f, 0.f);
        if (gr < N_NODES) av = *(const float4*)&A[gr * 128 + col];
        split_store(sAh, sAl, row * APAD + col, av);
    }
    __syncthreads();

    // ldmatrix lane addresses (byte offsets in shared space)
    uint32_t sb = (uint32_t)__cvta_generic_to_shared(smem);
    uint32_t aoff = (uint32_t)(((lane & 15) * APAD + (lane >> 4) * 8) * 2);
    uint32_t aH = sb + SMG_AH + aoff;
    uint32_t aL = sb + SMG_AL + aoff;
    uint32_t boff = (uint32_t)(((n0 + ((lane >> 4) << 3) + (lane & 7)) * WPAD
                                + (((lane >> 3) & 1) << 3)) * 2);
    uint32_t bH = sb + SMG_WH + boff;
    uint32_t bL = sb + SMG_WL + boff;

    float c[4][2][4];
#pragma unroll
    for (int m = 0; m < 4; m++)
#pragma unroll
        for (int g = 0; g < 2; g++)
#pragma unroll
            for (int q = 0; q < 4; q++) c[m][g][q] = 0.f;

#pragma unroll
    for (int pass = 0; pass < 3; pass++) {
        uint32_t ab = (pass == 2) ? aL : aH;
        uint32_t bb = (pass == 1) ? bL : bH;
#pragma unroll
        for (int k = 0; k < 8; k++) {
            uint32_t br[4];
            LDSM4(br, bb + k * 32);             // 16 bf16 cols = 32B
#pragma unroll
            for (int m = 0; m < 4; m++) {
                uint32_t ar[4];
                LDSM4(ar, ab + (uint32_t)((m * 16 * APAD + k * 16) * 2));
                MMA_BF16(c[m][0], ar, br[0], br[1]);
                MMA_BF16(c[m][1], ar, br[2], br[3]);
            }
        }
    }

    __syncthreads();   // all warps done reading sA before z-tile overlay

    // accumulators -> smem z tile (m16n8 f32 frag layout)
#pragma unroll
    for (int m = 0; m < 4; m++)
#pragma unroll
        for (int g = 0; g < 2; g++) {
            int row = m * 16 + (lane >> 2);
            int col = n0 + g * 8 + (lane & 3) * 2;
            *(float2*)&szt[row * ZPAD + col] = make_float2(c[m][g][0], c[m][g][1]);
            *(float2*)&szt[(row + 8) * ZPAD + col] = make_float2(c[m][g][2], c[m][g][3]);
        }
    __syncthreads();

    // s_src / s_dst: thread t -> row t>>2, quarter t&3 (32 cols), 4-lane reduce
    {
        int r = tid >> 2, q = tid & 3;
        const float* zr = szt + r * ZPAD + q * 32;
        float ps = 0.f, pd = 0.f;
#pragma unroll
        for (int cc = 0; cc < 32; cc++) {
            float v = zr[cc];
            ps += v * asrc[q * 32 + cc];
            pd += v * adst[q * 32 + cc];
        }
        ps += __shfl_xor_sync(0xffffffffu, ps, 1);
        pd += __shfl_xor_sync(0xffffffffu, pd, 1);
        ps += __shfl_xor_sync(0xffffffffu, ps, 2);
        pd += __shfl_xor_sync(0xffffffffu, pd, 2);
        int gr = i0 + r;
        if (q == 0 && gr < N_NODES) { g_ssrc[gr] = ps; g_sdst[gr] = pd; }
    }

    // coalesced fp16 z store (4 halfs = 8B per thread-iter)
#pragma unroll
    for (int t = 0; t < 8; t++) {
        int idx = tid + t * 256;
        int row = idx >> 5, col = (idx & 31) * 4;
        int gr = i0 + row;
        if (gr < N_NODES) {
            float4 v = *(const float4*)&szt[row * ZPAD + col];
            __half2 p0 = __floats2half2_rn(v.x, v.y);
            __half2 p1 = __floats2half2_rn(v.z, v.w);
            uint2 pk;
            pk.x = *(uint32_t*)&p0;
            pk.y = *(uint32_t*)&p1;
            *(uint2*)&g_zh[gr * 128 + col] = pk;
        }
    }
}

// ---------------- histogram of dst (int4, 4 atomics per thread) ----------------
__global__ __launch_bounds__(256) void hist_kernel(const int* __restrict__ dst) {
    int i = blockIdx.x * blockDim.x + threadIdx.x;   // int4 index
    if (i * 4 < N_EDGES) {
        int4 d = *(const int4*)&dst[i * 4];
        atomicAdd(&g_cnt[d.x], 1);
        atomicAdd(&g_cnt[d.y], 1);
        atomicAdd(&g_cnt[d.z], 1);
        atomicAdd(&g_cnt[d.w], 1);
    }
}

// ---------------- parallel scan, phase 1 ----------------
__global__ __launch_bounds__(1024) void scan1_kernel() {
    __shared__ int ws[32];
    int t = threadIdx.x, b = blockIdx.x;
    int i = b * 1024 + t;
    int lane = t & 31, w = t >> 5;
    int c = (i < N_NODES) ? g_cnt[i] : 0;
    int v = c;
#pragma unroll
    for (int o = 1; o < 32; o <<= 1) {
        int n = __shfl_up_sync(0xffffffffu, v, o);
        if (lane >= o) v += n;
    }
    if (lane == 31) ws[w] = v;
    __syncthreads();
    if (w == 0) {
        int s = ws[lane];
#pragma unroll
        for (int o = 1; o < 32; o <<= 1) {
            int n = __shfl_up_sync(0xffffffffu, s, o);
            if (lane >= o) s += n;
        }
        ws[lane] = s;
    }
    __syncthreads();
    int pre = (w > 0) ? ws[w - 1] : 0;
    if (i < N_NODES) g_lex[i] = pre + v - c;
    if (t == 0) g_bsum[b] = ws[31];
}

// ---------------- phase 2+3 merged: every block scans the 49 block sums -------
__global__ __launch_bounds__(256) void scan23_kernel() {
    __shared__ int sb[64];
    int t = threadIdx.x;
    if (t < 64) {
        int v = (t < NB_SCAN) ? g_bsum[t] : 0;
        sb[t] = v;
    }
    __syncthreads();
    if (t < 64) {
        int v = sb[t];
        int incl = v;
#pragma unroll
        for (int o = 1; o < 64; o <<= 1) {
            int n = (t >= o) ? sb[t - o] : 0;
            __syncthreads();
            incl += n;
            sb[t] = incl;
            __syncthreads();
        }
        sb[t] = incl - v;   // exclusive prefix
    } else {
#pragma unroll
        for (int o = 1; o < 64; o <<= 1) { __syncthreads(); __syncthreads(); }
    }
    __syncthreads();
    int i = blockIdx.x * blockDim.x + t;
    if (i < N_NODES) {
        int off = g_lex[i] + sb[i >> 10];
        g_off[i] = off;
        g_cur[i] = off;
    }
}

// ---------------- fused per-edge score + CSR scatter ----------------
// 4 lanes per edge, 2 independent float4 loads per lane (MLP=2).
#define DOT4(A, B) ((A).x*(B).x + (A).y*(B).y + (A).z*(B).z + (A).w*(B).w)

__global__ __launch_bounds__(256) void edge_fused_kernel(const float* __restrict__ efeats,
                                                         const float* __restrict__ Wattn,
                                                         const int* __restrict__ src,
                                                         const int* __restrict__ dst) {
    int gid = blockIdx.x * blockDim.x + threadIdx.x;
    int e = gid >> 2;
    int l = gid & 3;
    if (e >= N_EDGES) return;
    const float* erow = &efeats[e * EDIM + l * 8];
    float4 ev0 = *(const float4*)&erow[0];
    float4 ev1 = *(const float4*)&erow[4];
    float4 av0 = *(const float4*)&Wattn[DIM + l * 8];
    float4 av1 = *(const float4*)&Wattn[DIM + l * 8 + 4];
    float p = DOT4(ev0, av0) + DOT4(ev1, av1);
    p += __shfl_xor_sync(0xffffffffu, p, 2);
    p += __shfl_xor_sync(0xffffffffu, p, 1);
    if (l == 0) {
        int s = src[e];
        int d = dst[e];
        float t = p + g_ssrc[s];
        int pos = atomicAdd(&g_cur[d], 1);
        g_pair[pos] = make_uint2((unsigned)s, __float_as_uint(t));
    }
}

// ---------------- warp-per-node single-pass softmax + aggregation -------------
__device__ __forceinline__ float4 ldz_h4(const __half* p) {
    uint2 r = *(const uint2*)p;
    __half2 h0 = *(__half2*)&r.x;
    __half2 h1 = *(__half2*)&r.y;
    float2 f0 = __half22float2(h0);
    float2 f1 = __half22float2(h1);
    return make_float4(f0.x, f0.y, f1.x, f1.y);
}

__global__ __launch_bounds__(256) void aggregate_kernel(float* __restrict__ h) {
    int gid = blockIdx.x * blockDim.x + threadIdx.x;
    int node = gid >> 5;
    int lane = gid & 31;
    if (node >= N_NODES) return;

    int beg = g_off[node];
    int end = g_off[node + 1];

    float acc0 = 0.f, acc1 = 0.f, acc2 = 0.f, acc3 = 0.f;

    if (beg < end) {
        float sd = g_sdst[node];
        float lsum = 0.f;

        for (int j0 = beg; j0 < end; j0 += 32) {
            int j = j0 + lane;
            float wgt = 0.f;
            int sidx = 0;
            if (j < end) {
                uint2 pr = g_pair[j];
                float x = __uint_as_float(pr.y) + sd;
                x = x > 0.f ? x : 0.01f * x;
                wgt = __expf(x);
                sidx = (int)pr.x;
            }
            lsum += wgt;
            int cnt = end - j0;
            if (cnt > 32) cnt = 32;
            int q = 0;
            for (; q + 4 <= cnt; q += 4) {
                float a0 = __shfl_sync(0xffffffffu, wgt, q + 0);
                float a1 = __shfl_sync(0xffffffffu, wgt, q + 1);
                float a2 = __shfl_sync(0xffffffffu, wgt, q + 2);
                float a3 = __shfl_sync(0xffffffffu, wgt, q + 3);
                int s0 = __shfl_sync(0xffffffffu, sidx, q + 0);
                int s1 = __shfl_sync(0xffffffffu, sidx, q + 1);
                int s2 = __shfl_sync(0xffffffffu, sidx, q + 2);
                int s3 = __shfl_sync(0xffffffffu, sidx, q + 3);
                float4 z0 = ldz_h4(&g_zh[s0 * 128 + lane * 4]);
                float4 z1 = ldz_h4(&g_zh[s1 * 128 + lane * 4]);
                float4 z2 = ldz_h4(&g_zh[s2 * 128 + lane * 4]);
                float4 z3 = ldz_h4(&g_zh[s3 * 128 + lane * 4]);
                acc0 += a0 * z0.x; acc1 += a0 * z0.y; acc2 += a0 * z0.z; acc3 += a0 * z0.w;
                acc0 += a1 * z1.x; acc1 += a1 * z1.y; acc2 += a1 * z1.z; acc3 += a1 * z1.w;
                acc0 += a2 * z2.x; acc1 += a2 * z2.y; acc2 += a2 * z2.z; acc3 += a2 * z2.w;
                acc0 += a3 * z3.x; acc1 += a3 * z3.y; acc2 += a3 * z3.z; acc3 += a3 * z3.w;
            }
            for (; q < cnt; q++) {
                float al = __shfl_sync(0xffffffffu, wgt, q);
                int sq = __shfl_sync(0xffffffffu, sidx, q);
                float4 zv = ldz_h4(&g_zh[sq * 128 + lane * 4]);
                acc0 += al * zv.x; acc1 += al * zv.y; acc2 += al * zv.z; acc3 += al * zv.w;
            }
        }

#pragma unroll
        for (int o = 16; o; o >>= 1) lsum += __shfl_xor_sync(0xffffffffu, lsum, o);
        float inv = 1.0f / lsum;
        acc0 *= inv; acc1 *= inv; acc2 *= inv; acc3 *= inv;
    }

    float4 o4 = make_float4(acc0, acc1, acc2, acc3);
    *(float4*)&h[node * 128 + lane * 4] = o4;
}

// ---------------- launcher (single stream; overlap measured neutral) ----------
extern "C" void kernel_launch(void* const* d_in, const int* in_sizes, int n_in,
                              void* d_out, int out_size) {
    const float* nfeats = (const float*)d_in[0];
    const float* efeats = (const float*)d_in[1];
    const float* W_fc   = (const float*)d_in[2];
    const float* W_attn = (const float*)d_in[3];
    const int*   src    = (const int*)d_in[4];
    const int*   dst    = (const int*)d_in[5];
    float* out = (float*)d_out;

    cudaFuncSetAttribute(gemm_mma_kernel, cudaFuncAttributeMaxDynamicSharedMemorySize,
                         SMG_TOTAL);

    init_kernel<<<(N_NODES + 255) / 256, 256>>>();
    gemm_mma_kernel<<<(N_NODES + 63) / 64, 256, SMG_TOTAL>>>(nfeats, W_fc, W_attn);
    hist_kernel<<<(N_EDGES / 4 + 255) / 256, 256>>>(dst);
    scan1_kernel<<<NB_SCAN, 1024>>>();
    scan23_kernel<<<(N_NODES + 255) / 256, 256>>>();
    edge_fused_kernel<<<(N_EDGES * 4 + 255) / 256, 256>>>(efeats, W_attn, src, dst);
    aggregate_kernel<<<(N_NODES * 32 + 255) / 256, 256>>>(out);
}